// round 5
// baseline (speedup 1.0000x reference)
#include <cuda_runtime.h>

#define SX 512
#define NG (SX * SX)
#define MAXM 8192
#define NT 1024

// ---- global scratch (no clears needed; all reads are guarded by freshly
// built occupancy bits, so stale values are unreachable) ----
__device__ int g_cid[NG];    // voxel id -> compact id (valid only where occ set this run)
__device__ int g_pvox[MAXM]; // per-point voxel id

// voxelization: must match jnp: floor((p - (-51.2f)) / 0.2f) in fp32
__device__ __forceinline__ int voxel_of(float px, float py) {
    int cx = (int)floorf((px - (-51.2f)) / 0.2f);
    int cy = (int)floorf((py - (-51.2f)) / 0.2f);
    cx = min(max(cx, 0), SX - 1);
    cy = min(max(cy, 0), SX - 1);
    return cy * SX + cx;
}

// full-chip pre-pass: strided point loads done with all SMs
__global__ void k_prevox(const float* __restrict__ pts, int N) {
    int i = blockIdx.x * blockDim.x + threadIdx.x;
    if (i < N) g_pvox[i] = voxel_of(pts[i * 5 + 1], pts[i * 5 + 2]);
}

// ---- shared memory layout (bytes) ----
#define OFF_OCC    0        // u32[8192]  occupancy bitmap           32KB
#define OFF_CORE   32768    // u32[8192]  core bitmap                32KB
#define OFF_VOX    65536    // int[8192]  cid -> voxel id            32KB
#define OFF_PARENT 98304    // u16[8192]  union-find / later denseR  16KB
#define OFF_RCID   114688   // u16[8192]  cid -> root cid            16KB
#define OFF_RAWV   131072   // int[8192]  cid -> raw/dense/final     32KB
#define OFF_COUNTS 163840   // u32[8192]  voxel count per dense id   32KB
#define OFF_ROOTS  196608   // int[8192]  root voxel ids             32KB
#define OFF_CTR    229376   // int[3]     M, R, maxinst
#define SMEM_BYTES (229376 + 16)

__global__ void k_main(int N, float* __restrict__ out, int out_size) {
    extern __shared__ unsigned char sm[];
    unsigned int*   occ    = (unsigned int*)(sm + OFF_OCC);
    unsigned int*   corew  = (unsigned int*)(sm + OFF_CORE);
    int*            vox    = (int*)(sm + OFF_VOX);
    unsigned short* parent = (unsigned short*)(sm + OFF_PARENT);
    unsigned short* rcid   = (unsigned short*)(sm + OFF_RCID);
    int*            rawv   = (int*)(sm + OFF_RAWV);
    unsigned int*   counts = (unsigned int*)(sm + OFF_COUNTS);
    int*            roots  = (int*)(sm + OFF_ROOTS);
    int*            ctr    = (int*)(sm + OFF_CTR); // [0]=M [1]=R [2]=maxinst

    const int tid = threadIdx.x;

    // P0: clear bitmaps + counts + counters
    for (int w = tid; w < NG / 32; w += NT) { occ[w] = 0; corew[w] = 0; counts[w] = 0; }
    if (tid == 0) { ctr[0] = 0; ctr[1] = 0; ctr[2] = 0; }
    __syncthreads();

    // P1: occupancy + compact id assignment (first setter appends)
    for (int i = tid; i < N; i += NT) {
        int v = g_pvox[i];
        unsigned mask = 1u << (v & 31);
        unsigned old = atomicOr(&occ[v >> 5], mask);
        if (!(old & mask)) {
            int c = atomicAdd(&ctr[0], 1);
            vox[c] = v;
            g_cid[v] = c;
            parent[c] = (unsigned short)c;
        }
    }
    __syncthreads();
    const int M = ctr[0];

    // P2: core = occupied && >=5 occupied in 3x3 (eps=1.5 => 8-neighborhood, self incl)
    for (int c = tid; c < M; c += NT) {
        int v = vox[c], x = v & (SX - 1), y = v >> 9;
        int cnt = 0;
        #pragma unroll
        for (int dy = -1; dy <= 1; dy++) {
            int ny = y + dy;
            if (ny < 0 || ny >= SX) continue;
            #pragma unroll
            for (int dx = -1; dx <= 1; dx++) {
                int nx = x + dx;
                if (nx < 0 || nx >= SX) continue;
                int n = ny * SX + nx;
                cnt += (occ[n >> 5] >> (n & 31)) & 1u;
            }
        }
        if (cnt >= 5) atomicOr(&corew[v >> 5], 1u << (v & 31));
    }
    __syncthreads();

    // union-find helpers (smem, u16). Hooking compares VOXEL ids so the final
    // root of each component is its minimum voxel id — deterministic
    // regardless of compact-id assignment order or schedule.
    auto findh = [&](int xx) -> int {              // with path halving (union phase only)
        while (true) {
            int p = parent[xx];
            if (p == xx) return xx;
            int gp = parent[p];
            if (gp != p) parent[xx] = (unsigned short)gp;
            xx = p;
        }
    };
    auto unite = [&](int a, int b) {
        int ra = findh(a), rb = findh(b);
        while (ra != rb) {
            if (vox[ra] < vox[rb]) { int t = ra; ra = rb; rb = t; }
            // ra has larger voxel id: hook under rb
            unsigned short prev = atomicCAS(&parent[ra], (unsigned short)ra, (unsigned short)rb);
            if (prev == (unsigned short)ra) return;
            ra = findh(prev);
            rb = findh(rb);
        }
    };

    // P3: union over core-core 8-edges (each undirected edge once)
    for (int c = tid; c < M; c += NT) {
        int v = vox[c];
        if (!((corew[v >> 5] >> (v & 31)) & 1u)) continue;
        int x = v & (SX - 1), y = v >> 9;
        const int dd[4][2] = {{-1, 0}, {-1, -1}, {0, -1}, {1, -1}};
        #pragma unroll
        for (int k = 0; k < 4; k++) {
            int nx = x + dd[k][0], ny = y + dd[k][1];
            if (nx < 0 || nx >= SX || ny < 0) continue;
            int n = ny * SX + nx;
            if ((corew[n >> 5] >> (n & 31)) & 1u) unite(c, g_cid[n]);
        }
    }
    __syncthreads();

    // P4: flatten READ-ONLY (parent static now => deterministic)
    for (int c = tid; c < M; c += NT) {
        int xx = c, p = parent[xx];
        while (p != xx) { xx = p; p = parent[xx]; }
        rcid[c] = (unsigned short)xx;
    }
    __syncthreads();

    // P5: raw root-voxel label per cell; collect roots
    for (int c = tid; c < M; c += NT) {
        int v = vox[c];
        bool iscore = (corew[v >> 5] >> (v & 31)) & 1u;
        if (iscore) {
            int rc = rcid[c];
            rawv[c] = vox[rc];
            if (rc == c) { int idx = atomicAdd(&ctr[1], 1); roots[idx] = v; }
        } else {
            int best = 0x7fffffff;
            int x = v & (SX - 1), y = v >> 9;
            #pragma unroll
            for (int dy = -1; dy <= 1; dy++) {
                int ny = y + dy;
                if (ny < 0 || ny >= SX) continue;
                #pragma unroll
                for (int dx = -1; dx <= 1; dx++) {
                    int nx = x + dx;
                    if (nx < 0 || nx >= SX) continue;
                    int n = ny * SX + nx;
                    if ((corew[n >> 5] >> (n & 31)) & 1u)
                        best = min(best, vox[rcid[g_cid[n]]]);
                }
            }
            rawv[c] = (best == 0x7fffffff) ? -1 : best;
        }
    }
    __syncthreads();
    const int R = ctr[1];

    // P6: dense id per root = rank of its voxel id among all root voxel ids
    //     (order-invariant wrt the atomic-append order of roots[]).
    //     parent[] is dead now — reuse it to store dense ids at root cids.
    for (int c = tid; c < M; c += NT) {
        int v = vox[c];
        if (((corew[v >> 5] >> (v & 31)) & 1u) && rcid[c] == c) {
            int rank = 0;
            for (int j = 0; j < R; j++) rank += (roots[j] < v);
            parent[c] = (unsigned short)rank;
        }
    }
    __syncthreads();

    // P7: per-voxel dense label + voxel counts per cluster (rawv := dense id)
    for (int c = tid; c < M; c += NT) {
        int rv = rawv[c];
        if (rv >= 0) {
            int d = parent[g_cid[rv]];
            atomicAdd(&counts[d], 1u);
            rawv[c] = d;
        }
    }
    __syncthreads();

    // P8: drop clusters with < 20 voxels; track max instance id (rawv := final)
    for (int c = tid; c < M; c += NT) {
        int d = rawv[c];
        int f = (d >= 0 && counts[d] >= 20) ? d : -1;
        rawv[c] = f;
        atomicMax(&ctr[2], f + 1);
    }
    __syncthreads();

    // P9: scatter to points; append max_num_inst
    for (int i = tid; i < N; i += NT)
        out[i] = (float)rawv[g_cid[g_pvox[i]]];
    if (tid == 0 && out_size > N) out[N] = (float)ctr[2];
}

extern "C" void kernel_launch(void* const* d_in, const int* in_sizes, int n_in,
                              void* d_out, int out_size) {
    const float* pts = (const float*)d_in[0];
    int N = in_sizes[0] / 5;
    if (N > MAXM) N = MAXM;
    float* out = (float*)d_out;

    cudaFuncSetAttribute(k_main, cudaFuncAttributeMaxDynamicSharedMemorySize, SMEM_BYTES);
    k_prevox<<<(N + 255) / 256, 256>>>(pts, N);
    k_main<<<1, NT, SMEM_BYTES>>>(N, out, out_size);
}

// round 8
// speedup vs baseline: 1.8185x; 1.8185x over previous
#include <cuda_runtime.h>

#define SX 512
#define NG (SX * SX)
#define NW (NG / 32)
#define MAXM 8192
#define CL 8          // cluster size (portable max)
#define NT 1024
#define TOT (CL * NT)

// ---- global scratch. g_cid is never cleared: every read of it is guarded by
// occupancy/core bits rebuilt each run, so stale entries are unreachable. ----
__device__ int      g_cid[NG];     // voxel id -> compact id (this run)
__device__ unsigned g_occ[NW];     // occupancy bitmap
__device__ unsigned g_corb[NW];    // core bitmap
__device__ int      g_vox[MAXM];   // cid -> voxel id
__device__ int      g_parent[MAXM];// union-find parent; later dense-rank at roots
__device__ int      g_rcid[MAXM];  // cid -> root cid
__device__ int      g_rawv[MAXM];  // cid -> raw root voxel / dense id / final
__device__ int      g_counts[MAXM];// dense id -> voxel count
__device__ int      g_roots[MAXM]; // root voxel ids (unordered)
__device__ int      g_pvox[MAXM];  // point -> voxel id
__device__ int      g_ctr[4];      // [0]=M [1]=R [2]=maxinst

// voxelization: must match jnp: floor((p - (-51.2f)) / 0.2f) in fp32
__device__ __forceinline__ int voxel_of(float px, float py) {
    int cx = (int)floorf((px - (-51.2f)) / 0.2f);
    int cy = (int)floorf((py - (-51.2f)) / 0.2f);
    cx = min(max(cx, 0), SX - 1);
    cy = min(max(cy, 0), SX - 1);
    return cy * SX + cx;
}

// Cluster-wide phase barrier WITH memory ordering:
// __threadfence() (gpu scope >= cluster) publishes stores to L2 and emits
// CCTL.IVALL so post-barrier loads refetch from coherent L2 (sm_103a L1s are
// not coherent across SMs; a bare barrier.cluster does NOT order memory).
__device__ __forceinline__ void csync() {
    __threadfence();
    asm volatile("barrier.cluster.arrive.aligned;" ::: "memory");
    asm volatile("barrier.cluster.wait.aligned;" ::: "memory");
}

__device__ __forceinline__ bool getbit(const unsigned* bm, int v) {
    return (bm[v >> 5] >> (v & 31)) & 1u;
}

// find with path halving — used ONLY inside the union phase; races quiesce at
// the cluster barrier. All reads via __ldcg (L2) so no warp can spin on a
// stale L1 line. Hooking compares VOXEL ids, so final roots are component
// minima regardless of schedule or cid assignment order.
__device__ int ffind(int x) {
    while (true) {
        int p = __ldcg(&g_parent[x]);
        if (p == x) return x;
        int gp = __ldcg(&g_parent[p]);
        if (gp != p) g_parent[x] = gp;   // benign race; quiesces at barrier
        x = p;
    }
}

__device__ void funite(int a, int b) {
    int ra = ffind(a), rb = ffind(b);
    while (ra != rb) {
        if (g_vox[ra] < g_vox[rb]) { int t = ra; ra = rb; rb = t; }
        int prev = atomicCAS(&g_parent[ra], ra, rb);  // hook larger-vox root under smaller
        if (prev == ra) return;
        ra = ffind(prev);
        rb = ffind(rb);
    }
}

__global__ void __cluster_dims__(CL, 1, 1)
k_main(const float* __restrict__ pts, int N, float* __restrict__ out, int out_size) {
    const int gtid = blockIdx.x * NT + threadIdx.x;
    const int lane = threadIdx.x & 31;

    // P0: clear bitmaps + counts + counters
    for (int w = gtid; w < NW; w += TOT) { g_occ[w] = 0; g_corb[w] = 0; }
    for (int w = gtid; w < MAXM; w += TOT) g_counts[w] = 0;
    if (gtid == 0) { g_ctr[0] = 0; g_ctr[1] = 0; g_ctr[2] = 0; }
    csync();

    // P1: occupancy + warp-aggregated compact-id assignment
    int Npad = (N + 31) & ~31;
    for (int i = gtid; i < Npad; i += TOT) {
        bool act = i < N;
        int v = 0; bool app = false;
        if (act) {
            v = voxel_of(pts[i * 5 + 1], pts[i * 5 + 2]);
            g_pvox[i] = v;
            unsigned m = 1u << (v & 31);
            unsigned old = atomicOr(&g_occ[v >> 5], m);
            app = !(old & m);
        }
        unsigned ball = __ballot_sync(0xffffffffu, app);
        if (ball) {
            int leader = __ffs(ball) - 1;
            int base = 0;
            if (lane == leader) base = atomicAdd(&g_ctr[0], __popc(ball));
            base = __shfl_sync(0xffffffffu, base, leader);
            if (app) {
                int c = base + __popc(ball & ((1u << lane) - 1u));
                g_vox[c] = v;
                g_cid[v] = c;
                g_parent[c] = c;
            }
        }
    }
    csync();
    const int M = __ldcg(&g_ctr[0]);

    // P2: core = occupied && >=5 occupied in 3x3 (eps=1.5 => 8-neighborhood, self incl)
    for (int c = gtid; c < M; c += TOT) {
        int v = g_vox[c], x = v & (SX - 1), y = v >> 9;
        int cnt = 0;
        #pragma unroll
        for (int dy = -1; dy <= 1; dy++) {
            int ny = y + dy;
            if (ny < 0 || ny >= SX) continue;
            #pragma unroll
            for (int dx = -1; dx <= 1; dx++) {
                int nx = x + dx;
                if (nx < 0 || nx >= SX) continue;
                cnt += (int)getbit(g_occ, ny * SX + nx);
            }
        }
        if (cnt >= 5) atomicOr(&g_corb[v >> 5], 1u << (v & 31));
    }
    csync();

    // P3: union over core-core 8-edges (each undirected edge once)
    for (int c = gtid; c < M; c += TOT) {
        int v = g_vox[c];
        if (!getbit(g_corb, v)) continue;
        int x = v & (SX - 1), y = v >> 9;
        if (x > 0 && getbit(g_corb, v - 1)) funite(c, g_cid[v - 1]);
        if (y > 0) {
            if (x > 0 && getbit(g_corb, v - SX - 1)) funite(c, g_cid[v - SX - 1]);
            if (getbit(g_corb, v - SX))              funite(c, g_cid[v - SX]);
            if (x < SX - 1 && getbit(g_corb, v - SX + 1)) funite(c, g_cid[v - SX + 1]);
        }
    }
    csync();

    // P4: flatten READ-ONLY via L2 (g_parent static now => deterministic roots)
    for (int c = gtid; c < M; c += TOT) {
        int xx = c, p = __ldcg(&g_parent[xx]);
        while (p != xx) { xx = p; p = __ldcg(&g_parent[xx]); }
        g_rcid[c] = xx;
    }
    csync();

    // P5: raw root-voxel label per cell; collect root list
    for (int c = gtid; c < M; c += TOT) {
        int v = g_vox[c];
        if (getbit(g_corb, v)) {
            int rc = g_rcid[c];
            g_rawv[c] = g_vox[rc];
            if (rc == c) { int idx = atomicAdd(&g_ctr[1], 1); g_roots[idx] = v; }
        } else {
            int best = 0x7fffffff;
            int x = v & (SX - 1), y = v >> 9;
            #pragma unroll
            for (int dy = -1; dy <= 1; dy++) {
                int ny = y + dy;
                if (ny < 0 || ny >= SX) continue;
                #pragma unroll
                for (int dx = -1; dx <= 1; dx++) {
                    int nx = x + dx;
                    if (nx < 0 || nx >= SX) continue;
                    int n = ny * SX + nx;
                    if (getbit(g_corb, n)) best = min(best, g_vox[g_rcid[g_cid[n]]]);
                }
            }
            g_rawv[c] = (best == 0x7fffffff) ? -1 : best;
        }
    }
    csync();
    const int R = __ldcg(&g_ctr[1]);

    // P6: dense id per root = rank of its voxel id among all root voxel ids
    //     (order-invariant wrt append order). g_parent is dead — store ranks there.
    for (int c = gtid; c < M; c += TOT) {
        if (g_rcid[c] == c && getbit(g_corb, g_vox[c])) {
            int v = g_vox[c], rank = 0;
            for (int j = 0; j < R; j++) rank += (g_roots[j] < v);
            g_parent[c] = rank;
        }
    }
    csync();

    // P7: per-voxel dense label + voxel counts per cluster (g_rawv := dense id)
    for (int c = gtid; c < M; c += TOT) {
        int rv = g_rawv[c];
        if (rv >= 0) {
            int d = g_parent[g_cid[rv]];
            atomicAdd(&g_counts[d], 1);
            g_rawv[c] = d;
        }
    }
    csync();

    // P8: drop clusters < 20 voxels; warp-reduced max instance id
    int Mpad = (M + 31) & ~31;
    for (int c = gtid; c < Mpad; c += TOT) {
        int f = -1;
        if (c < M) {
            int d = g_rawv[c];
            f = (d >= 0 && g_counts[d] >= 20) ? d : -1;
            g_rawv[c] = f;
        }
        int wmax = __reduce_max_sync(0xffffffffu, f + 1);
        if (lane == 0 && wmax > 0) atomicMax(&g_ctr[2], wmax);
    }
    csync();

    // P9: scatter to points; append max_num_inst
    for (int i = gtid; i < N; i += TOT)
        out[i] = (float)g_rawv[g_cid[g_pvox[i]]];
    if (gtid == 0 && out_size > N) out[N] = (float)__ldcg(&g_ctr[2]);
}

extern "C" void kernel_launch(void* const* d_in, const int* in_sizes, int n_in,
                              void* d_out, int out_size) {
    const float* pts = (const float*)d_in[0];
    int N = in_sizes[0] / 5;
    if (N > MAXM) N = MAXM;
    float* out = (float*)d_out;

    k_main<<<CL, NT>>>(pts, N, out, out_size);
}